// round 14
// baseline (speedup 1.0000x reference)
#include <cuda_runtime.h>
#include <cuda_bf16.h>
#include <cuda_fp16.h>
#include <math.h>
#include <stdint.h>

#define Bx 128
#define Lx 256
#define HIDx 768
#define HID2x 1536
#define CDIMx 192
#define SDIMx 128
#define NPROJx 128
#define FDIMx 321
#define BIGF 1000000000.0f

// ---------------- scratch ----------------
__device__ float g_rep[Bx * HID2x];
__device__ float g_Pt[(size_t)Bx * NPROJx * Lx];    // [b][p][l]
__device__ float g_feat[Bx * FDIMx];                // only col 320 (d_ot) used
__device__ float g_partial[32 * Bx * 320];          // split-K partials (z=32)
__device__ int   g_mcnt[Bx];

// ---------------- helpers ----------------
__device__ __forceinline__ uint32_t smem_u32(const void* p) {
    uint32_t a;
    asm("{ .reg .u64 t; cvta.to.shared.u64 t, %1; cvt.u32.u64 %0, t; }" : "=r"(a) : "l"(p));
    return a;
}

__device__ __forceinline__ uint2 cvt4_f16(float4 v) {
    uint32_t h0, h1;
    asm("cvt.rn.f16x2.f32 %0, %1, %2;" : "=r"(h0) : "f"(v.y), "f"(v.x));
    asm("cvt.rn.f16x2.f32 %0, %1, %2;" : "=r"(h1) : "f"(v.w), "f"(v.z));
    return make_uint2(h0, h1);
}

#define LDSM4(R0, R1, R2, R3, ADDR) \
    asm volatile("ldmatrix.sync.aligned.m8n8.x4.shared.b16 {%0,%1,%2,%3}, [%4];" \
        : "=r"(R0), "=r"(R1), "=r"(R2), "=r"(R3) : "r"(ADDR))

#define MMA_F16(D, A, B) \
    asm volatile("mma.sync.aligned.m16n8k16.row.col.f32.f16.f16.f32 " \
        "{%0,%1,%2,%3}, {%4,%5,%6,%7}, {%8,%9}, {%0,%1,%2,%3};" \
        : "+f"((D)[0]), "+f"((D)[1]), "+f"((D)[2]), "+f"((D)[3]) \
        : "r"((A)[0]), "r"((A)[1]), "r"((A)[2]), "r"((A)[3]), \
          "r"((B)[0]), "r"((B)[1]))

// ===== K12 fused: k1 role (CTAs 0..383) + k2 role (CTAs 384..639) =====
#define K12_SMEM 32768

__global__ void __launch_bounds__(256, 2) k12_fused(const float* __restrict__ H,
                                                    const int* __restrict__ tt,
                                                    const int* __restrict__ m,
                                                    const float* __restrict__ proj) {
    extern __shared__ char dyn[];
    int tid = threadIdx.x;

    if (blockIdx.x < 384) {
        // ---------------- k1 role: masked means + cls -> g_rep ----------------
        int bid = blockIdx.x;
        int b = bid / 3, c = bid % 3;
        float* sf0 = reinterpret_cast<float*>(dyn);        // 256
        float* sf1 = sf0 + 256;
        __shared__ float sc01[2];

        int t = tt[b * Lx + tid];
        int mm = m[b * Lx + tid];
        sf0[tid] = (t == 0 && mm == 1) ? 1.f : 0.f;
        sf1[tid] = (t == 1 && mm == 1) ? 1.f : 0.f;
        __syncthreads();

        if (tid == 0) {
            int c0 = 0, c1 = 0;
            for (int l = 0; l < Lx; l++) { c0 += (sf0[l] > 0.5f); c1 += (sf1[l] > 0.5f); }
            if (c == 0) {
                g_mcnt[b] = min(c0, c1);
                g_feat[b * FDIMx + 320] = 0.f;
            }
            sc01[0] = fmaxf((float)c0, 1.f);
            sc01[1] = fmaxf((float)c1, 1.f);
        }
        __syncthreads();

        int h = c * 256 + tid;
        const float* Hb = H + (size_t)b * Lx * HIDx;
        const float* Hp = Hb + h;

        float a0 = 0.f, a1 = 0.f, a2 = 0.f, a3 = 0.f;
        float d0 = 0.f, d1 = 0.f, d2 = 0.f, d3 = 0.f;
#pragma unroll 4
        for (int l = 0; l < Lx; l += 4) {
            float v0 = Hp[(size_t)(l + 0) * HIDx];
            float v1 = Hp[(size_t)(l + 1) * HIDx];
            float v2 = Hp[(size_t)(l + 2) * HIDx];
            float v3 = Hp[(size_t)(l + 3) * HIDx];
            a0 += sf0[l + 0] * v0; d0 += sf1[l + 0] * v0;
            a1 += sf0[l + 1] * v1; d1 += sf1[l + 1] * v1;
            a2 += sf0[l + 2] * v2; d2 += sf1[l + 2] * v2;
            a3 += sf0[l + 3] * v3; d3 += sf1[l + 3] * v3;
        }
        float s0 = (a0 + a1) + (a2 + a3);
        float s1 = (d0 + d1) + (d2 + d3);
        g_rep[(size_t)b * HID2x + h]        = Hb[h];
        g_rep[(size_t)b * HID2x + HIDx + h] = s0 / sc01[0] - s1 / sc01[1];
    } else {
        // ---------------- k2 role: fp16 HMMA, both operands cvt'd at load ----------------
        char* sm = dyn;
        uint32_t sb = smem_u32(sm);
        int bid = blockIdx.x - 384;
        int b = bid >> 1;
        int l0 = (bid & 1) * 128;
        int lane = tid & 31, w = tid >> 5;
        int wm = w >> 2;
        int wn = w & 3;

        int srow = tid >> 1;
        int half = tid & 1;
        const float4* gA = reinterpret_cast<const float4*>(H + ((size_t)(b * Lx) + l0 + srow) * HIDx) + half * 4;
        const float4* gBf = reinterpret_cast<const float4*>(proj + (size_t)srow * HIDx) + half * 4;
        int sw_s = (srow >> 1) & 3;
        uint32_t o0 = (uint32_t)srow * 64 + (uint32_t)(((half * 2)     ^ sw_s) * 16);
        uint32_t o1 = (uint32_t)srow * 64 + (uint32_t)(((half * 2 + 1) ^ sw_s) * 16);

        uint32_t rowA[4]; uint32_t swA[4];
#pragma unroll
        for (int i = 0; i < 4; i++) {
            int r = wm * 64 + i * 16 + (lane & 15);
            rowA[i] = (uint32_t)r * 64;
            swA[i] = (uint32_t)((r >> 1) & 3);
        }
        uint32_t ua = (uint32_t)(lane >> 4);
        uint32_t rowB[2]; uint32_t swB[2];
#pragma unroll
        for (int j2 = 0; j2 < 2; j2++) {
            int r = wn * 32 + j2 * 16 + (lane & 7) + ((lane >> 4) << 3);
            rowB[j2] = (uint32_t)r * 64;
            swB[j2] = (uint32_t)((r >> 1) & 3);
        }
        uint32_t ub = (uint32_t)((lane >> 3) & 1);

        float acc[4][4][4];
#pragma unroll
        for (int i = 0; i < 4; i++)
#pragma unroll
            for (int j = 0; j < 4; j++)
#pragma unroll
                for (int r = 0; r < 4; r++) acc[i][j][r] = 0.f;

        uint4 pfA[2], pfB[2];
        {
            float4 t0 = gA[0], t1 = gA[1], t2 = gA[2], t3 = gA[3];
            uint2 c0 = cvt4_f16(t0), c1 = cvt4_f16(t1), c2 = cvt4_f16(t2), c3 = cvt4_f16(t3);
            pfA[0] = make_uint4(c0.x, c0.y, c1.x, c1.y);
            pfA[1] = make_uint4(c2.x, c2.y, c3.x, c3.y);
            t0 = gBf[0]; t1 = gBf[1]; t2 = gBf[2]; t3 = gBf[3];
            c0 = cvt4_f16(t0); c1 = cvt4_f16(t1); c2 = cvt4_f16(t2); c3 = cvt4_f16(t3);
            pfB[0] = make_uint4(c0.x, c0.y, c1.x, c1.y);
            pfB[1] = make_uint4(c2.x, c2.y, c3.x, c3.y);
            char* sp = sm;
            *reinterpret_cast<uint4*>(sp + 0 + o0) = pfA[0];
            *reinterpret_cast<uint4*>(sp + 0 + o1) = pfA[1];
            *reinterpret_cast<uint4*>(sp + 8192 + o0) = pfB[0];
            *reinterpret_cast<uint4*>(sp + 8192 + o1) = pfB[1];
        }
        __syncthreads();

        for (int c = 0; c < 24; c++) {
            int buf = c & 1;
            if (c < 23) {
                int off = (c + 1) * 8;
                float4 t0 = gA[off], t1 = gA[off + 1], t2 = gA[off + 2], t3 = gA[off + 3];
                uint2 c0 = cvt4_f16(t0), c1 = cvt4_f16(t1), c2 = cvt4_f16(t2), c3 = cvt4_f16(t3);
                pfA[0] = make_uint4(c0.x, c0.y, c1.x, c1.y);
                pfA[1] = make_uint4(c2.x, c2.y, c3.x, c3.y);
                t0 = gBf[off]; t1 = gBf[off + 1]; t2 = gBf[off + 2]; t3 = gBf[off + 3];
                c0 = cvt4_f16(t0); c1 = cvt4_f16(t1); c2 = cvt4_f16(t2); c3 = cvt4_f16(t3);
                pfB[0] = make_uint4(c0.x, c0.y, c1.x, c1.y);
                pfB[1] = make_uint4(c2.x, c2.y, c3.x, c3.y);
            }

            uint32_t bb = sb + (uint32_t)buf * 16384;
#pragma unroll
            for (int sel = 0; sel < 2; sel++) {
                uint32_t u2 = (uint32_t)(sel * 2);
                uint32_t bf[4][2];
#pragma unroll
                for (int j2 = 0; j2 < 2; j2++) {
                    uint32_t ah = bb + 8192 + rowB[j2] + (((u2 + ub) ^ swB[j2]) << 4);
                    uint32_t r0, r1, r2, r3;
                    LDSM4(r0, r1, r2, r3, ah);
                    bf[j2 * 2][0] = r0; bf[j2 * 2][1] = r1;
                    bf[j2 * 2 + 1][0] = r2; bf[j2 * 2 + 1][1] = r3;
                }
                uint32_t af[4][4];
#pragma unroll
                for (int i = 0; i < 4; i++) {
                    uint32_t a = bb + rowA[i] + (((u2 + ua) ^ swA[i]) << 4);
                    LDSM4(af[i][0], af[i][1], af[i][2], af[i][3], a);
                }
#pragma unroll
                for (int i = 0; i < 4; i++)
#pragma unroll
                    for (int j = 0; j < 4; j++) {
                        MMA_F16(acc[i][j], af[i], bf[j]);
                    }
            }

            if (c < 23) {
                char* sp = sm + (1 - buf) * 16384;
                *reinterpret_cast<uint4*>(sp + 0 + o0) = pfA[0];
                *reinterpret_cast<uint4*>(sp + 0 + o1) = pfA[1];
                *reinterpret_cast<uint4*>(sp + 8192 + o0) = pfB[0];
                *reinterpret_cast<uint4*>(sp + 8192 + o1) = pfB[1];
            }
            __syncthreads();
        }

        float* gp = g_Pt + (size_t)b * NPROJx * Lx + l0;
#pragma unroll
        for (int i = 0; i < 4; i++) {
            int lrow = wm * 64 + i * 16 + (lane >> 2);
#pragma unroll
            for (int j = 0; j < 4; j++) {
                int p = wn * 32 + j * 8 + (lane & 3) * 2;
                gp[(size_t)p * Lx + lrow]           = acc[i][j][0];
                gp[(size_t)(p + 1) * Lx + lrow]     = acc[i][j][1];
                gp[(size_t)p * Lx + lrow + 8]       = acc[i][j][2];
                gp[(size_t)(p + 1) * Lx + lrow + 8] = acc[i][j][3];
            }
        }
    }
}

// ===== sort helpers (contiguous-run bitonic) =====
__device__ __forceinline__ void cexA(float& a, float& b) {
    float mn = fminf(a, b);
    b = fmaxf(a, b);
    a = mn;
}
__device__ __forceinline__ void cexD(float& a, float& b) {
    float mx = fmaxf(a, b);
    b = fminf(a, b);
    a = mx;
}
__device__ __forceinline__ void cexP(float& a, float& b, bool asc) {
    float mn = asc ? fminf(a, b) : fmaxf(a, b);
    float mx = asc ? fmaxf(a, b) : fminf(a, b);
    a = mn; b = mx;
}
__device__ __forceinline__ void merge8(float v[8], bool asc) {
    cexP(v[0], v[4], asc); cexP(v[1], v[5], asc); cexP(v[2], v[6], asc); cexP(v[3], v[7], asc);
    cexP(v[0], v[2], asc); cexP(v[1], v[3], asc); cexP(v[4], v[6], asc); cexP(v[5], v[7], asc);
    cexP(v[0], v[1], asc); cexP(v[2], v[3], asc); cexP(v[4], v[5], asc); cexP(v[6], v[7], asc);
}
__device__ __forceinline__ void cross8(float v[8], int s, bool keepmin) {
#pragma unroll
    for (int r = 0; r < 8; r++) {
        float o = __shfl_xor_sync(0xffffffffu, v[r], s);
        v[r] = keepmin ? fminf(v[r], o) : fmaxf(v[r], o);
    }
}
__device__ __forceinline__ void sort256v2(float v[8], int lane) {
    cexA(v[0], v[1]); cexD(v[2], v[3]); cexA(v[4], v[5]); cexD(v[6], v[7]);
    cexA(v[0], v[2]); cexA(v[1], v[3]); cexD(v[4], v[6]); cexD(v[5], v[7]);
    cexA(v[0], v[1]); cexA(v[2], v[3]); cexD(v[4], v[5]); cexD(v[6], v[7]);
    bool a8 = (lane & 1) == 0;
    merge8(v, a8);
    bool a16 = (lane & 2) == 0;
    cross8(v, 1, ((lane & 1) == 0) == a16);
    merge8(v, a16);
    bool a32 = (lane & 4) == 0;
    cross8(v, 2, ((lane & 2) == 0) == a32);
    cross8(v, 1, ((lane & 1) == 0) == a32);
    merge8(v, a32);
    bool a64 = (lane & 8) == 0;
    cross8(v, 4, ((lane & 4) == 0) == a64);
    cross8(v, 2, ((lane & 2) == 0) == a64);
    cross8(v, 1, ((lane & 1) == 0) == a64);
    merge8(v, a64);
    bool a128 = (lane & 16) == 0;
    cross8(v, 8, ((lane & 8) == 0) == a128);
    cross8(v, 4, ((lane & 4) == 0) == a128);
    cross8(v, 2, ((lane & 2) == 0) == a128);
    cross8(v, 1, ((lane & 1) == 0) == a128);
    merge8(v, a128);
    cross8(v, 16, (lane & 16) == 0);
    cross8(v, 8,  (lane & 8) == 0);
    cross8(v, 4,  (lane & 4) == 0);
    cross8(v, 2,  (lane & 2) == 0);
    cross8(v, 1,  (lane & 1) == 0);
    merge8(v, true);
}

// ===== FK: fused k3 (sort, CTAs 0..2047) + k4a (feature GEMM, CTAs 2048..2687) =====
#define FK_SMEM 18432

__global__ void __launch_bounds__(256) k34_fused(const int* __restrict__ tt,
                                                 const int* __restrict__ m,
                                                 const float* __restrict__ Wc,
                                                 const float* __restrict__ Ws) {
    extern __shared__ char dyn[];
    int tid = threadIdx.x;

    if (blockIdx.x < 2048) {
        int bid = blockIdx.x;
        int b = bid >> 4;
        int px = bid & 15;
        int warp = tid >> 5, lane = tid & 31;
        float* sgrp = reinterpret_cast<float*>(dyn);

        int p = px * 8 + warp;
        const float* col = g_Pt + ((size_t)b * NPROJx + p) * Lx;

        float4 va = reinterpret_cast<const float4*>(col)[lane * 2];
        float4 vb = reinterpret_cast<const float4*>(col)[lane * 2 + 1];
        int4 ta = reinterpret_cast<const int4*>(tt + b * Lx)[lane * 2];
        int4 tb = reinterpret_cast<const int4*>(tt + b * Lx)[lane * 2 + 1];
        int4 ma = reinterpret_cast<const int4*>(m + b * Lx)[lane * 2];
        int4 mb = reinterpret_cast<const int4*>(m + b * Lx)[lane * 2 + 1];

        float raw[8] = {va.x, va.y, va.z, va.w, vb.x, vb.y, vb.z, vb.w};
        int tvs[8] = {ta.x, ta.y, ta.z, ta.w, tb.x, tb.y, tb.z, tb.w};
        int mvs[8] = {ma.x, ma.y, ma.z, ma.w, mb.x, mb.y, mb.z, mb.w};

        float v[8];
#pragma unroll
        for (int r = 0; r < 8; r++) {
            int tg = (mvs[r] == 1) ? tvs[r] : 2;
            float base = (tg == 2) ? BIGF : raw[r];
            uint32_t u = (__float_as_uint(base) & ~1u) | (uint32_t)(tg != 0);
            v[r] = __uint_as_float(u);
        }
        sort256v2(v, lane);

        int g[8];
        int cl = 0;
#pragma unroll
        for (int r = 0; r < 8; r++) {
            g[r] = (int)(__float_as_uint(v[r]) & 1u);
            cl += g[r];
        }
        int inc = cl;
#pragma unroll
        for (int o = 1; o < 32; o <<= 1) {
            int n = __shfl_up_sync(0xffffffffu, inc, o);
            if (lane >= o) inc += n;
        }
        int c1 = inc - cl;

        float* s0 = sgrp + warp * 512;
        float* s1 = s0 + 256;
#pragma unroll
        for (int r = 0; r < 8; r++) {
            float val = __uint_as_float(__float_as_uint(v[r]) & ~1u);
            int idx = lane * 8 + r;
            if (g[r]) { s1[c1] = val; c1++; }
            else      { s0[idx - c1] = val; }
        }
        __syncwarp();

        int mc = g_mcnt[b];
        float s = 0.f;
#pragma unroll
        for (int r = 0; r < 8; r++) {
            int i = r * 32 + lane;
            if (i < mc) s += fabsf(s0[i] - s1[i]);
        }
#pragma unroll
        for (int o = 16; o > 0; o >>= 1) s += __shfl_down_sync(0xffffffffu, s, o);

        if (lane == 0) {
            float mean = s / (float)max(mc, 1);
            atomicMax(reinterpret_cast<int*>(&g_feat[b * FDIMx + 320]), __float_as_int(mean));
        }
    } else {
        int idx = blockIdx.x - 2048;
        int ftile = (idx % 5) * 64;
        int btile = ((idx / 5) & 3) * 32;
        int kc    = (idx / 20) * 48;

        float* repS = reinterpret_cast<float*>(dyn);
        float* wS   = repS + 48 * 32;

        int tx = tid & 15;
        int ty = tid >> 4;

#pragma unroll
        for (int s = 0; s < 3; s++) {
#pragma unroll
            for (int q = 0; q < 2; q++) {
                int e = tid + q * 256;
                int kk = e & 15, bb = e >> 4;
                repS[(s * 16 + kk) * 32 + bb] = g_rep[(size_t)(btile + bb) * HID2x + kc + s * 16 + kk];
            }
#pragma unroll
            for (int q = 0; q < 4; q++) {
                int e = tid + q * 256;
                int kk = e & 15, ff = e >> 4;
                int f = ftile + ff;
                const float* Wr = (f < CDIMx) ? (Wc + (size_t)f * HID2x)
                                              : (Ws + (size_t)(f - CDIMx) * HID2x);
                wS[(s * 16 + kk) * 64 + ff] = Wr[kc + s * 16 + kk];
            }
        }
        __syncthreads();

        float acc[2][4];
#pragma unroll
        for (int i = 0; i < 2; i++)
#pragma unroll
            for (int j = 0; j < 4; j++) acc[i][j] = 0.f;

#pragma unroll 8
        for (int kk = 0; kk < 48; kk++) {
            float4 wv = *reinterpret_cast<const float4*>(&wS[kk * 64 + tx * 4]);
            float r0 = repS[kk * 32 + ty * 2];
            float r1 = repS[kk * 32 + ty * 2 + 1];
            acc[0][0] += r0 * wv.x; acc[0][1] += r0 * wv.y;
            acc[0][2] += r0 * wv.z; acc[0][3] += r0 * wv.w;
            acc[1][0] += r1 * wv.x; acc[1][1] += r1 * wv.y;
            acc[1][2] += r1 * wv.z; acc[1][3] += r1 * wv.w;
        }

        int z = idx / 20;
#pragma unroll
        for (int i = 0; i < 2; i++) {
            int bb = btile + ty * 2 + i;
            float4 o = make_float4(acc[i][0], acc[i][1], acc[i][2], acc[i][3]);
            *reinterpret_cast<float4*>(&g_partial[((size_t)z * Bx + bb) * 320 + ftile + tx * 4]) = o;
        }
    }
}

// ===== K5: combine split-K + gate, LayerNorm(321), classifier (paired reductions) =====
__device__ __forceinline__ float2 blockReduceSum2(float2 val, float2* sbuf) {
    int tid = threadIdx.x;
#pragma unroll
    for (int o = 16; o > 0; o >>= 1) {
        val.x += __shfl_down_sync(0xffffffffu, val.x, o);
        val.y += __shfl_down_sync(0xffffffffu, val.y, o);
    }
    if ((tid & 31) == 0) sbuf[tid >> 5] = val;
    __syncthreads();
    if (tid < 32) {
        int nw = (blockDim.x + 31) >> 5;
        float2 r = (tid < nw) ? sbuf[tid] : make_float2(0.f, 0.f);
#pragma unroll
        for (int o = 16; o > 0; o >>= 1) {
            r.x += __shfl_down_sync(0xffffffffu, r.x, o);
            r.y += __shfl_down_sync(0xffffffffu, r.y, o);
        }
        if (tid == 0) sbuf[32] = r;
    }
    __syncthreads();
    float2 out = sbuf[32];
    __syncthreads();
    return out;
}

__global__ void k5_ln_cls(const float* __restrict__ bc,
                          const float* __restrict__ bs,
                          const float* __restrict__ gate,
                          const float* __restrict__ ln_g,
                          const float* __restrict__ ln_b,
                          const float* __restrict__ Wcls,
                          const float* __restrict__ bcls,
                          float* __restrict__ out) {
    __shared__ float2 sbuf[33];
    int b = blockIdx.x;
    int f = threadIdx.x; // 384 threads
    bool act = (f < FDIMx);

    float x = 0.f;
    if (f < 320) {
        float s = 0.f;
#pragma unroll
        for (int z = 0; z < 32; z++) s += g_partial[((size_t)z * Bx + b) * 320 + f];
        float g = 1.f / (1.f + expf(-gate[0]));
        if (f < CDIMx) x = (s + bc[f]) * (1.f - g);
        else           x = (s + bs[f - CDIMx]) * g;
    } else if (f == 320) {
        x = g_feat[b * FDIMx + 320];
    }

    float2 ss = blockReduceSum2(make_float2(x, x * x), sbuf);
    float mean = ss.x / (float)FDIMx;
    float var  = ss.y / (float)FDIMx - mean * mean;
    float inv  = rsqrtf(var + 1e-5f);

    float nrm = act ? ((x - mean) * inv * ln_g[f] + ln_b[f]) : 0.f;
    float w0 = act ? Wcls[f] : 0.f;
    float w1 = act ? Wcls[FDIMx + f] : 0.f;

    float2 cls = blockReduceSum2(make_float2(nrm * w0, nrm * w1), sbuf);
    if (f == 0) {
        out[b * 2 + 0] = cls.x + bcls[0];
        out[b * 2 + 1] = cls.y + bcls[1];
    }
}

// =================================== launch ======================================
extern "C" void kernel_launch(void* const* d_in, const int* in_sizes, int n_in,
                              void* d_out, int out_size) {
    const float* H    = (const float*)d_in[0];
    const int*   tt   = (const int*)d_in[1];
    const int*   m    = (const int*)d_in[2];
    const float* Wc   = (const float*)d_in[3];
    const float* bc   = (const float*)d_in[4];
    const float* Ws   = (const float*)d_in[5];
    const float* bs   = (const float*)d_in[6];
    const float* gate = (const float*)d_in[7];
    const float* ln_g = (const float*)d_in[8];
    const float* ln_b = (const float*)d_in[9];
    const float* Wcls = (const float*)d_in[10];
    const float* bcls = (const float*)d_in[11];
    const float* proj = (const float*)d_in[12];
    float* out = (float*)d_out;

    cudaFuncSetAttribute(k12_fused, cudaFuncAttributeMaxDynamicSharedMemorySize, K12_SMEM);

    k12_fused<<<640, 256, K12_SMEM>>>(H, tt, m, proj);
    k34_fused<<<2688, 256, FK_SMEM>>>(tt, m, Wc, Ws);
    k5_ln_cls<<<Bx, 384>>>(bc, bs, gate, ln_g, ln_b, Wcls, bcls, out);
}

// round 15
// speedup vs baseline: 1.1074x; 1.1074x over previous
#include <cuda_runtime.h>
#include <cuda_bf16.h>
#include <cuda_fp16.h>
#include <math.h>
#include <stdint.h>

#define Bx 128
#define Lx 256
#define HIDx 768
#define HID2x 1536
#define CDIMx 192
#define SDIMx 128
#define NPROJx 128
#define FDIMx 321
#define BIGF 1000000000.0f

// ---------------- scratch ----------------
__device__ float g_rep[Bx * HID2x];
__device__ float g_Pt[(size_t)Bx * NPROJx * Lx];    // [b][p][l]
__device__ float g_feat[Bx * FDIMx];                // only col 320 (d_ot) used
__device__ float g_partial[32 * Bx * 320];          // split-K partials (z=32)
__device__ int   g_mcnt[Bx];
__device__ unsigned short g_ph[NPROJx * HIDx];      // proj as fp16

// ---------------- helpers ----------------
__device__ __forceinline__ uint32_t smem_u32(const void* p) {
    uint32_t a;
    asm("{ .reg .u64 t; cvta.to.shared.u64 t, %1; cvt.u32.u64 %0, t; }" : "=r"(a) : "l"(p));
    return a;
}

__device__ __forceinline__ uint2 cvt4_f16(float4 v) {
    uint32_t h0, h1;
    asm("cvt.rn.f16x2.f32 %0, %1, %2;" : "=r"(h0) : "f"(v.y), "f"(v.x));
    asm("cvt.rn.f16x2.f32 %0, %1, %2;" : "=r"(h1) : "f"(v.w), "f"(v.z));
    return make_uint2(h0, h1);
}

#define LDSM4(R0, R1, R2, R3, ADDR) \
    asm volatile("ldmatrix.sync.aligned.m8n8.x4.shared.b16 {%0,%1,%2,%3}, [%4];" \
        : "=r"(R0), "=r"(R1), "=r"(R2), "=r"(R3) : "r"(ADDR))

#define MMA_F16(D, A, B) \
    asm volatile("mma.sync.aligned.m16n8k16.row.col.f32.f16.f16.f32 " \
        "{%0,%1,%2,%3}, {%4,%5,%6,%7}, {%8,%9}, {%0,%1,%2,%3};" \
        : "+f"((D)[0]), "+f"((D)[1]), "+f"((D)[2]), "+f"((D)[3]) \
        : "r"((A)[0]), "r"((A)[1]), "r"((A)[2]), "r"((A)[3]), \
          "r"((B)[0]), "r"((B)[1]))

// ===== K1: 512 threads, l-split, 4-acc ILP; gridDim.y==3 slice does proj cvt =====
__global__ void __launch_bounds__(512) k1_stats(const float* __restrict__ H,
                                                const int* __restrict__ tt,
                                                const int* __restrict__ m,
                                                const float* __restrict__ proj) {
    int b = blockIdx.x;
    int c = blockIdx.y;   // 0..2 = h-chunks; 3 = proj conversion slice
    int tid = threadIdx.x;

    if (c == 3) {
        int i = b * 512 + tid;
        if (i < (NPROJx * HIDx / 4)) {
            float4 v = reinterpret_cast<const float4*>(proj)[i];
            reinterpret_cast<uint2*>(g_ph)[i] = cvt4_f16(v);
        }
        return;
    }

    __shared__ float sf0[Lx], sf1[Lx];
    __shared__ float ps[2][2][256];
    __shared__ float sc0, sc1;

    int hl = tid & 255;
    int lh = tid >> 8;     // 0/1: which l-half

    if (tid < 256) {
        int t = tt[b * Lx + tid];
        int mm = m[b * Lx + tid];
        sf0[tid] = (t == 0 && mm == 1) ? 1.f : 0.f;
        sf1[tid] = (t == 1 && mm == 1) ? 1.f : 0.f;
    }
    __syncthreads();

    if (tid == 0) {
        int c0 = 0, c1 = 0;
        for (int l = 0; l < Lx; l++) { c0 += (sf0[l] > 0.5f); c1 += (sf1[l] > 0.5f); }
        if (c == 0) {
            g_mcnt[b] = min(c0, c1);
            g_feat[b * FDIMx + 320] = 0.f;
        }
        sc0 = fmaxf((float)c0, 1.f);
        sc1 = fmaxf((float)c1, 1.f);
    }

    int h = c * 256 + hl;
    const float* Hb = H + (size_t)b * Lx * HIDx;
    const float* Hp = Hb + (size_t)(lh * 128) * HIDx + h;
    const float* f0p = sf0 + lh * 128;
    const float* f1p = sf1 + lh * 128;

    float a0 = 0.f, a1 = 0.f, a2 = 0.f, a3 = 0.f;
    float b0 = 0.f, b1 = 0.f, b2 = 0.f, b3 = 0.f;
#pragma unroll 8
    for (int l = 0; l < 128; l += 4) {
        float v0 = Hp[(size_t)(l + 0) * HIDx];
        float v1 = Hp[(size_t)(l + 1) * HIDx];
        float v2 = Hp[(size_t)(l + 2) * HIDx];
        float v3 = Hp[(size_t)(l + 3) * HIDx];
        a0 += f0p[l + 0] * v0; b0 += f1p[l + 0] * v0;
        a1 += f0p[l + 1] * v1; b1 += f1p[l + 1] * v1;
        a2 += f0p[l + 2] * v2; b2 += f1p[l + 2] * v2;
        a3 += f0p[l + 3] * v3; b3 += f1p[l + 3] * v3;
    }
    ps[0][lh][hl] = (a0 + a1) + (a2 + a3);
    ps[1][lh][hl] = (b0 + b1) + (b2 + b3);
    __syncthreads();

    if (tid < 256) {
        float s0 = ps[0][0][hl] + ps[0][1][hl];
        float s1 = ps[1][0][hl] + ps[1][1][hl];
        g_rep[(size_t)b * HID2x + h]        = Hb[h];
        g_rep[(size_t)b * HID2x + HIDx + h] = s0 / sc0 - s1 / sc1;
    }
}

// ============ K2 (fp16 HMMA single-pass, fused cvt, 128lx128p) ============
#define K2_SMEM 32768

__global__ void __launch_bounds__(256, 2) k2_hmma(const float* __restrict__ H) {
    extern __shared__ char sm[];
    uint32_t sb = smem_u32(sm);
    int b = blockIdx.x;
    int l0 = blockIdx.y * 128;
    int tid = threadIdx.x;
    int lane = tid & 31, w = tid >> 5;
    int wm = w >> 2;
    int wn = w & 3;

    int srow = tid >> 1;
    int half = tid & 1;
    const float4* gA = reinterpret_cast<const float4*>(H + ((size_t)(b * Lx) + l0 + srow) * HIDx) + half * 4;
    const uint4* gB = reinterpret_cast<const uint4*>(g_ph + (size_t)srow * HIDx) + half * 2;
    int sw_s = (srow >> 1) & 3;
    uint32_t o0 = (uint32_t)srow * 64 + (uint32_t)(((half * 2)     ^ sw_s) * 16);
    uint32_t o1 = (uint32_t)srow * 64 + (uint32_t)(((half * 2 + 1) ^ sw_s) * 16);

    uint32_t rowA[4]; uint32_t swA[4];
#pragma unroll
    for (int i = 0; i < 4; i++) {
        int r = wm * 64 + i * 16 + (lane & 15);
        rowA[i] = (uint32_t)r * 64;
        swA[i] = (uint32_t)((r >> 1) & 3);
    }
    uint32_t ua = (uint32_t)(lane >> 4);
    uint32_t rowB[2]; uint32_t swB[2];
#pragma unroll
    for (int j2 = 0; j2 < 2; j2++) {
        int r = wn * 32 + j2 * 16 + (lane & 7) + ((lane >> 4) << 3);
        rowB[j2] = (uint32_t)r * 64;
        swB[j2] = (uint32_t)((r >> 1) & 3);
    }
    uint32_t ub = (uint32_t)((lane >> 3) & 1);

    float acc[4][4][4];
#pragma unroll
    for (int i = 0; i < 4; i++)
#pragma unroll
        for (int j = 0; j < 4; j++)
#pragma unroll
            for (int r = 0; r < 4; r++) acc[i][j][r] = 0.f;

    float4 pfA[4];
    uint4 pfB[2];
    {
#pragma unroll
        for (int q = 0; q < 4; q++) pfA[q] = gA[q];
        pfB[0] = gB[0]; pfB[1] = gB[1];
        char* sp = sm;
        uint2 a0 = cvt4_f16(pfA[0]);
        uint2 a1 = cvt4_f16(pfA[1]);
        uint2 a2 = cvt4_f16(pfA[2]);
        uint2 a3 = cvt4_f16(pfA[3]);
        *reinterpret_cast<uint4*>(sp + 0 + o0) = make_uint4(a0.x, a0.y, a1.x, a1.y);
        *reinterpret_cast<uint4*>(sp + 0 + o1) = make_uint4(a2.x, a2.y, a3.x, a3.y);
        *reinterpret_cast<uint4*>(sp + 8192 + o0) = pfB[0];
        *reinterpret_cast<uint4*>(sp + 8192 + o1) = pfB[1];
    }
    __syncthreads();

    for (int c = 0; c < 24; c++) {
        int buf = c & 1;
        if (c < 23) {
            int offA = (c + 1) * 8;
            int offB = (c + 1) * 4;
#pragma unroll
            for (int q = 0; q < 4; q++) pfA[q] = gA[offA + q];
            pfB[0] = gB[offB]; pfB[1] = gB[offB + 1];
        }

        uint32_t bb = sb + (uint32_t)buf * 16384;
#pragma unroll
        for (int sel = 0; sel < 2; sel++) {
            uint32_t u2 = (uint32_t)(sel * 2);
            uint32_t bf[4][2];
#pragma unroll
            for (int j2 = 0; j2 < 2; j2++) {
                uint32_t ah = bb + 8192 + rowB[j2] + (((u2 + ub) ^ swB[j2]) << 4);
                uint32_t r0, r1, r2, r3;
                LDSM4(r0, r1, r2, r3, ah);
                bf[j2 * 2][0] = r0; bf[j2 * 2][1] = r1;
                bf[j2 * 2 + 1][0] = r2; bf[j2 * 2 + 1][1] = r3;
            }
            uint32_t af[4][4];
#pragma unroll
            for (int i = 0; i < 4; i++) {
                uint32_t a = bb + rowA[i] + (((u2 + ua) ^ swA[i]) << 4);
                LDSM4(af[i][0], af[i][1], af[i][2], af[i][3], a);
            }
#pragma unroll
            for (int i = 0; i < 4; i++)
#pragma unroll
                for (int j = 0; j < 4; j++) {
                    MMA_F16(acc[i][j], af[i], bf[j]);
                }
        }

        if (c < 23) {
            char* sp = sm + (1 - buf) * 16384;
            uint2 a0 = cvt4_f16(pfA[0]);
            uint2 a1 = cvt4_f16(pfA[1]);
            uint2 a2 = cvt4_f16(pfA[2]);
            uint2 a3 = cvt4_f16(pfA[3]);
            *reinterpret_cast<uint4*>(sp + 0 + o0) = make_uint4(a0.x, a0.y, a1.x, a1.y);
            *reinterpret_cast<uint4*>(sp + 0 + o1) = make_uint4(a2.x, a2.y, a3.x, a3.y);
            *reinterpret_cast<uint4*>(sp + 8192 + o0) = pfB[0];
            *reinterpret_cast<uint4*>(sp + 8192 + o1) = pfB[1];
        }
        __syncthreads();
    }

    float* gp = g_Pt + (size_t)b * NPROJx * Lx + l0;
#pragma unroll
    for (int i = 0; i < 4; i++) {
        int lrow = wm * 64 + i * 16 + (lane >> 2);
#pragma unroll
        for (int j = 0; j < 4; j++) {
            int p = wn * 32 + j * 8 + (lane & 3) * 2;
            gp[(size_t)p * Lx + lrow]           = acc[i][j][0];
            gp[(size_t)(p + 1) * Lx + lrow]     = acc[i][j][1];
            gp[(size_t)p * Lx + lrow + 8]       = acc[i][j][2];
            gp[(size_t)(p + 1) * Lx + lrow + 8] = acc[i][j][3];
        }
    }
}

// ===== sort helpers (contiguous-run bitonic) =====
__device__ __forceinline__ void cexA(float& a, float& b) {
    float mn = fminf(a, b);
    b = fmaxf(a, b);
    a = mn;
}
__device__ __forceinline__ void cexD(float& a, float& b) {
    float mx = fmaxf(a, b);
    b = fminf(a, b);
    a = mx;
}
__device__ __forceinline__ void cexP(float& a, float& b, bool asc) {
    float mn = asc ? fminf(a, b) : fmaxf(a, b);
    float mx = asc ? fmaxf(a, b) : fminf(a, b);
    a = mn; b = mx;
}
__device__ __forceinline__ void merge8(float v[8], bool asc) {
    cexP(v[0], v[4], asc); cexP(v[1], v[5], asc); cexP(v[2], v[6], asc); cexP(v[3], v[7], asc);
    cexP(v[0], v[2], asc); cexP(v[1], v[3], asc); cexP(v[4], v[6], asc); cexP(v[5], v[7], asc);
    cexP(v[0], v[1], asc); cexP(v[2], v[3], asc); cexP(v[4], v[5], asc); cexP(v[6], v[7], asc);
}
__device__ __forceinline__ void cross8(float v[8], int s, bool keepmin) {
#pragma unroll
    for (int r = 0; r < 8; r++) {
        float o = __shfl_xor_sync(0xffffffffu, v[r], s);
        v[r] = keepmin ? fminf(v[r], o) : fmaxf(v[r], o);
    }
}
__device__ __forceinline__ void sort256v2(float v[8], int lane) {
    cexA(v[0], v[1]); cexD(v[2], v[3]); cexA(v[4], v[5]); cexD(v[6], v[7]);
    cexA(v[0], v[2]); cexA(v[1], v[3]); cexD(v[4], v[6]); cexD(v[5], v[7]);
    cexA(v[0], v[1]); cexA(v[2], v[3]); cexD(v[4], v[5]); cexD(v[6], v[7]);
    bool a8 = (lane & 1) == 0;
    merge8(v, a8);
    bool a16 = (lane & 2) == 0;
    cross8(v, 1, ((lane & 1) == 0) == a16);
    merge8(v, a16);
    bool a32 = (lane & 4) == 0;
    cross8(v, 2, ((lane & 2) == 0) == a32);
    cross8(v, 1, ((lane & 1) == 0) == a32);
    merge8(v, a32);
    bool a64 = (lane & 8) == 0;
    cross8(v, 4, ((lane & 4) == 0) == a64);
    cross8(v, 2, ((lane & 2) == 0) == a64);
    cross8(v, 1, ((lane & 1) == 0) == a64);
    merge8(v, a64);
    bool a128 = (lane & 16) == 0;
    cross8(v, 8, ((lane & 8) == 0) == a128);
    cross8(v, 4, ((lane & 4) == 0) == a128);
    cross8(v, 2, ((lane & 2) == 0) == a128);
    cross8(v, 1, ((lane & 1) == 0) == a128);
    merge8(v, a128);
    cross8(v, 16, (lane & 16) == 0);
    cross8(v, 8,  (lane & 8) == 0);
    cross8(v, 4,  (lane & 4) == 0);
    cross8(v, 2,  (lane & 2) == 0);
    cross8(v, 1,  (lane & 1) == 0);
    merge8(v, true);
}

// ===== FK: fused k4a (CTAs 0..639, scheduled first) + k3 (CTAs 640..2687) =====
#define FK_SMEM 18432

__global__ void __launch_bounds__(256) k34_fused(const int* __restrict__ tt,
                                                 const int* __restrict__ m,
                                                 const float* __restrict__ Wc,
                                                 const float* __restrict__ Ws) {
    extern __shared__ char dyn[];
    int tid = threadIdx.x;

    if (blockIdx.x >= 640) {
        // ---------------- k3: sort role ----------------
        int bid = blockIdx.x - 640;
        int b = bid >> 4;
        int px = bid & 15;
        int warp = tid >> 5, lane = tid & 31;
        float* sgrp = reinterpret_cast<float*>(dyn);

        int p = px * 8 + warp;
        const float* col = g_Pt + ((size_t)b * NPROJx + p) * Lx;

        float4 va = reinterpret_cast<const float4*>(col)[lane * 2];
        float4 vb = reinterpret_cast<const float4*>(col)[lane * 2 + 1];
        int4 ta = reinterpret_cast<const int4*>(tt + b * Lx)[lane * 2];
        int4 tb = reinterpret_cast<const int4*>(tt + b * Lx)[lane * 2 + 1];
        int4 ma = reinterpret_cast<const int4*>(m + b * Lx)[lane * 2];
        int4 mb = reinterpret_cast<const int4*>(m + b * Lx)[lane * 2 + 1];

        float raw[8] = {va.x, va.y, va.z, va.w, vb.x, vb.y, vb.z, vb.w};
        int tvs[8] = {ta.x, ta.y, ta.z, ta.w, tb.x, tb.y, tb.z, tb.w};
        int mvs[8] = {ma.x, ma.y, ma.z, ma.w, mb.x, mb.y, mb.z, mb.w};

        float v[8];
#pragma unroll
        for (int r = 0; r < 8; r++) {
            int tg = (mvs[r] == 1) ? tvs[r] : 2;
            float base = (tg == 2) ? BIGF : raw[r];
            uint32_t u = (__float_as_uint(base) & ~1u) | (uint32_t)(tg != 0);
            v[r] = __uint_as_float(u);
        }
        sort256v2(v, lane);

        int g[8];
        int cl = 0;
#pragma unroll
        for (int r = 0; r < 8; r++) {
            g[r] = (int)(__float_as_uint(v[r]) & 1u);
            cl += g[r];
        }
        int inc = cl;
#pragma unroll
        for (int o = 1; o < 32; o <<= 1) {
            int n = __shfl_up_sync(0xffffffffu, inc, o);
            if (lane >= o) inc += n;
        }
        int c1 = inc - cl;

        float* s0 = sgrp + warp * 512;
        float* s1 = s0 + 256;
#pragma unroll
        for (int r = 0; r < 8; r++) {
            float val = __uint_as_float(__float_as_uint(v[r]) & ~1u);
            int idx = lane * 8 + r;
            if (g[r]) { s1[c1] = val; c1++; }
            else      { s0[idx - c1] = val; }
        }
        __syncwarp();

        int mc = g_mcnt[b];
        float s = 0.f;
#pragma unroll
        for (int r = 0; r < 8; r++) {
            int i = r * 32 + lane;
            if (i < mc) s += fabsf(s0[i] - s1[i]);
        }
#pragma unroll
        for (int o = 16; o > 0; o >>= 1) s += __shfl_down_sync(0xffffffffu, s, o);

        if (lane == 0) {
            float mean = s / (float)max(mc, 1);
            atomicMax(reinterpret_cast<int*>(&g_feat[b * FDIMx + 320]), __float_as_int(mean));
        }
    } else {
        // ---------------- k4a: feature GEMM role (first 640 CTAs) ----------------
        int idx = blockIdx.x;            // 0..639
        int ftile = (idx % 5) * 64;
        int btile = ((idx / 5) & 3) * 32;
        int kc    = (idx / 20) * 48;     // z = 0..31

        float* repS = reinterpret_cast<float*>(dyn);
        float* wS   = repS + 48 * 32;

        int tx = tid & 15;
        int ty = tid >> 4;

#pragma unroll
        for (int s = 0; s < 3; s++) {
#pragma unroll
            for (int q = 0; q < 2; q++) {
                int e = tid + q * 256;
                int kk = e & 15, bb = e >> 4;
                repS[(s * 16 + kk) * 32 + bb] = g_rep[(size_t)(btile + bb) * HID2x + kc + s * 16 + kk];
            }
#pragma unroll
            for (int q = 0; q < 4; q++) {
                int e = tid + q * 256;
                int kk = e & 15, ff = e >> 4;
                int f = ftile + ff;
                const float* Wr = (f < CDIMx) ? (Wc + (size_t)f * HID2x)
                                              : (Ws + (size_t)(f - CDIMx) * HID2x);
                wS[(s * 16 + kk) * 64 + ff] = Wr[kc + s * 16 + kk];
            }
        }
        __syncthreads();

        float acc[2][4];
#pragma unroll
        for (int i = 0; i < 2; i++)
#pragma unroll
            for (int j = 0; j < 4; j++) acc[i][j] = 0.f;

#pragma unroll 8
        for (int kk = 0; kk < 48; kk++) {
            float4 wv = *reinterpret_cast<const float4*>(&wS[kk * 64 + tx * 4]);
            float r0 = repS[kk * 32 + ty * 2];
            float r1 = repS[kk * 32 + ty * 2 + 1];
            acc[0][0] += r0 * wv.x; acc[0][1] += r0 * wv.y;
            acc[0][2] += r0 * wv.z; acc[0][3] += r0 * wv.w;
            acc[1][0] += r1 * wv.x; acc[1][1] += r1 * wv.y;
            acc[1][2] += r1 * wv.z; acc[1][3] += r1 * wv.w;
        }

        int z = idx / 20;
#pragma unroll
        for (int i = 0; i < 2; i++) {
            int bb = btile + ty * 2 + i;
            float4 o = make_float4(acc[i][0], acc[i][1], acc[i][2], acc[i][3]);
            *reinterpret_cast<float4*>(&g_partial[((size_t)z * Bx + bb) * 320 + ftile + tx * 4]) = o;
        }
    }
}

// ===== K5: combine split-K + gate, LayerNorm(321), classifier (paired reductions) =====
__device__ __forceinline__ float2 blockReduceSum2(float2 val, float2* sbuf) {
    int tid = threadIdx.x;
#pragma unroll
    for (int o = 16; o > 0; o >>= 1) {
        val.x += __shfl_down_sync(0xffffffffu, val.x, o);
        val.y += __shfl_down_sync(0xffffffffu, val.y, o);
    }
    if ((tid & 31) == 0) sbuf[tid >> 5] = val;
    __syncthreads();
    if (tid < 32) {
        int nw = (blockDim.x + 31) >> 5;
        float2 r = (tid < nw) ? sbuf[tid] : make_float2(0.f, 0.f);
#pragma unroll
        for (int o = 16; o > 0; o >>= 1) {
            r.x += __shfl_down_sync(0xffffffffu, r.x, o);
            r.y += __shfl_down_sync(0xffffffffu, r.y, o);
        }
        if (tid == 0) sbuf[32] = r;
    }
    __syncthreads();
    float2 out = sbuf[32];
    __syncthreads();
    return out;
}

__global__ void k5_ln_cls(const float* __restrict__ bc,
                          const float* __restrict__ bs,
                          const float* __restrict__ gate,
                          const float* __restrict__ ln_g,
                          const float* __restrict__ ln_b,
                          const float* __restrict__ Wcls,
                          const float* __restrict__ bcls,
                          float* __restrict__ out) {
    __shared__ float2 sbuf[33];
    int b = blockIdx.x;
    int f = threadIdx.x; // 384 threads
    bool act = (f < FDIMx);

    float x = 0.f;
    if (f < 320) {
        float s = 0.f;
#pragma unroll
        for (int z = 0; z < 32; z++) s += g_partial[((size_t)z * Bx + b) * 320 + f];
        float g = 1.f / (1.f + expf(-gate[0]));
        if (f < CDIMx) x = (s + bc[f]) * (1.f - g);
        else           x = (s + bs[f - CDIMx]) * g;
    } else if (f == 320) {
        x = g_feat[b * FDIMx + 320];
    }

    float2 ss = blockReduceSum2(make_float2(x, x * x), sbuf);
    float mean = ss.x / (float)FDIMx;
    float var  = ss.y / (float)FDIMx - mean * mean;
    float inv  = rsqrtf(var + 1e-5f);

    float nrm = act ? ((x - mean) * inv * ln_g[f] + ln_b[f]) : 0.f;
    float w0 = act ? Wcls[f] : 0.f;
    float w1 = act ? Wcls[FDIMx + f] : 0.f;

    float2 cls = blockReduceSum2(make_float2(nrm * w0, nrm * w1), sbuf);
    if (f == 0) {
        out[b * 2 + 0] = cls.x + bcls[0];
        out[b * 2 + 1] = cls.y + bcls[1];
    }
}

// =================================== launch ======================================
extern "C" void kernel_launch(void* const* d_in, const int* in_sizes, int n_in,
                              void* d_out, int out_size) {
    const float* H    = (const float*)d_in[0];
    const int*   tt   = (const int*)d_in[1];
    const int*   m    = (const int*)d_in[2];
    const float* Wc   = (const float*)d_in[3];
    const float* bc   = (const float*)d_in[4];
    const float* Ws   = (const float*)d_in[5];
    const float* bs   = (const float*)d_in[6];
    const float* gate = (const float*)d_in[7];
    const float* ln_g = (const float*)d_in[8];
    const float* ln_b = (const float*)d_in[9];
    const float* Wcls = (const float*)d_in[10];
    const float* bcls = (const float*)d_in[11];
    const float* proj = (const float*)d_in[12];
    float* out = (float*)d_out;

    cudaFuncSetAttribute(k2_hmma, cudaFuncAttributeMaxDynamicSharedMemorySize, K2_SMEM);

    k1_stats<<<dim3(Bx, 4), 512>>>(H, tt, m, proj);
    k2_hmma<<<dim3(Bx, 2), 256, K2_SMEM>>>(H);
    k34_fused<<<2688, 256, FK_SMEM>>>(tt, m, Wc, Ws);
    k5_ln_cls<<<Bx, 384>>>(bc, bs, gate, ln_g, ln_b, Wcls, bcls, out);
}